// round 12
// baseline (speedup 1.0000x reference)
#include <cuda_runtime.h>
#include <cuda_fp16.h>
#include <math.h>
#include <stdint.h>

// Problem dims
#define LL 16
#define TT 2048
#define DD 2048
#define RR 128
#define KCAP 1024
#define WIN 64          // boundary fixup window (ranks KCAP-32 .. KCAP+32)
#define HW (WIN / 2)
#define FTOK 8          // boundary tokens per fixup block

// ---------------- scratch (device globals) ----------------
__device__ float g_probs[LL * TT];
__device__ int   g_flag[LL * TT];          // 1 = selected (s2 path)
__device__ int   g_sel [LL * KCAP];        // selected tokens, token order
__device__ int   g_idx0[LL * KCAP];        // unselected tokens, token order
__device__ int   g_bnd [LL * WIN];         // boundary tokens (approx-rank order)
__device__ float g_bndp[LL * WIN];         // exact probs for boundary tokens
// fp16 copies (round-to-nearest)
__device__ __half g_A   [(size_t)LL * TT * DD];   // hidden
__device__ __half g_Ws1t[(size_t)LL * DD * DD];   // W_s1^T [L,N,K]
__device__ __half g_Wr1t[(size_t)LL * RR * DD];   // W_r1^T [L,R,K]

// ---------------- PTX helpers (baseline ISA only) ----------------
__device__ __forceinline__ uint32_t smem_u32(const void* p) {
    uint32_t a;
    asm("{ .reg .u64 t; cvta.to.shared.u64 t, %1; cvt.u32.u64 %0, t; }" : "=r"(a) : "l"(p));
    return a;
}
#define CP16(dst, src) \
    asm volatile("cp.async.cg.shared.global [%0], [%1], 16;" :: "r"(dst), "l"(src))
#define CP_COMMIT() asm volatile("cp.async.commit_group;")
#define CP_WAIT(n)  asm volatile("cp.async.wait_group %0;" :: "n"(n))

__device__ __forceinline__ void ldsm_x4(uint32_t* r, uint32_t addr) {
    asm volatile("ldmatrix.sync.aligned.m8n8.x4.shared.b16 {%0,%1,%2,%3}, [%4];"
                 : "=r"(r[0]), "=r"(r[1]), "=r"(r[2]), "=r"(r[3]) : "r"(addr));
}
__device__ __forceinline__ void mma16816(float* d, const uint32_t* a,
                                         uint32_t b0, uint32_t b1) {
    asm volatile(
        "mma.sync.aligned.m16n8k16.row.col.f32.f16.f16.f32 "
        "{%0,%1,%2,%3}, {%4,%5,%6,%7}, {%8,%9}, {%0,%1,%2,%3};"
        : "+f"(d[0]), "+f"(d[1]), "+f"(d[2]), "+f"(d[3])
        : "r"(a[0]), "r"(a[1]), "r"(a[2]), "r"(a[3]), "r"(b0), "r"(b1));
}

// =====================================================================
// hidden f32 -> g_A fp16 (RN)
// =====================================================================
__global__ void split_hidden_kernel(const float4* __restrict__ h) {
    size_t i = (size_t)blockIdx.x * blockDim.x + threadIdx.x;   // < L*T*D/4
    float4 v = h[i];
    __half2 p0 = make_half2(__float2half_rn(v.x), __float2half_rn(v.y));
    __half2 p1 = make_half2(__float2half_rn(v.z), __float2half_rn(v.w));
    ((uint2*)g_A)[i] = make_uint2(*(uint32_t*)&p0, *(uint32_t*)&p1);
}

// =====================================================================
// W[l,k,n] f32 -> Wt[l,n,k] fp16 (RN)
// =====================================================================
template<bool S1>
__global__ void transpose_split_kernel(const float* __restrict__ W, int K, int N) {
    __shared__ float tile[32][33];
    const int l  = blockIdx.z;
    const int k0 = blockIdx.x * 32;
    const int n0 = blockIdx.y * 32;
    const int tx = threadIdx.x, ty = threadIdx.y;
    const float* Wl = W + (size_t)l * K * N;
    #pragma unroll
    for (int r = 0; r < 4; r++)
        tile[ty + r * 8][tx] = Wl[(size_t)(k0 + ty + r * 8) * N + n0 + tx];
    __syncthreads();
    __half* Wt = S1 ? g_Ws1t : g_Wr1t;
    #pragma unroll
    for (int r = 0; r < 4; r++) {
        int n = n0 + ty + r * 8;
        float v = tile[tx][ty + r * 8];
        Wt[((size_t)l * N + n) * K + k0 + tx] = __float2half_rn(v);
    }
}

// =====================================================================
// HMMA GEMM (fp16 single-pass, fp32 accum): C[128x128 tile] = A @ B^T.
// PITCH-40 smem, 2-stage cp.async, 256 threads (warps 4x2), 2 CTAs/SM.
// FUSE: router mode — no C store; epilogue computes
//       probs[t] = sigmoid( relu(acc + b_r1) . W_r2 + b_r2 ) directly.
// =====================================================================
#define PITCH 40                    // fp16 elts per smem row (32 + 8 pad)
#define MAT_ELT (128 * PITCH)       // 5120 elts per matrix
#define MAT_B   (MAT_ELT * 2)       // 10240 bytes
#define STG_B   (2 * MAT_B)         // A,B : 20480 bytes
#define NITER   (DD / 32)           // 64

template<bool GATHER, bool FUSE>
__global__ __launch_bounds__(256, 2)
void hmma_gemm_kernel(const float* __restrict__ bias,
                      float* __restrict__ Cout, int Ntot,
                      const float* __restrict__ W_r2,
                      const float* __restrict__ b_r2) {
    extern __shared__ __align__(16) char smraw[];
    const uint32_t smb = smem_u32(smraw);

    const int tid  = threadIdx.x;
    const int lane = tid & 31;
    const int wid  = tid >> 5;
    const int warp_m = wid & 3;
    const int warp_n = wid >> 2;
    const int mb = blockIdx.x, nb = blockIdx.y, l = blockIdx.z;

    __shared__ int s_rows[128];
    if (tid < 128)
        s_rows[tid] = GATHER ? g_idx0[l * KCAP + mb * 128 + tid] : (mb * 128 + tid);
    __syncthreads();

    const int c0 = tid, c1 = tid + 256;
    const int r0 = c0 >> 2, r1 = c1 >> 2;
    const int f0 = (c0 & 3) * 8, f1 = (c1 & 3) * 8;
    const __half* __restrict__ Aall = g_A + (size_t)l * TT * DD;
    const __half* __restrict__ Wt =
        (GATHER ? g_Ws1t : g_Wr1t) + ((size_t)l * Ntot + nb * 128) * DD;
    const __half* aPtr0 = Aall + (size_t)s_rows[r0] * DD + f0;
    const __half* aPtr1 = Aall + (size_t)s_rows[r1] * DD + f1;
    const __half* bPtr0 = Wt + (size_t)r0 * DD + f0;
    const __half* bPtr1 = Wt + (size_t)r1 * DD + f1;
    const uint32_t d0 = (uint32_t)(r0 * PITCH + f0) * 2;
    const uint32_t d1 = (uint32_t)(r1 * PITCH + f1) * 2;

    float acc[2][8][4];
    #pragma unroll
    for (int mt = 0; mt < 2; mt++)
        #pragma unroll
        for (int nt = 0; nt < 8; nt++)
            #pragma unroll
            for (int q = 0; q < 4; q++) acc[mt][nt][q] = 0.0f;

    const uint32_t aoff = (uint32_t)((warp_m * 32 + (lane & 15)) * PITCH + (lane >> 4) * 8) * 2;
    const uint32_t boff = (uint32_t)((warp_n * 64 + (lane & 15)) * PITCH + (lane >> 4) * 8) * 2;

    auto load_stage = [&](int s, int kt) {
        uint32_t b = smb + s * STG_B;
        CP16(b + d0,         aPtr0 + kt);
        CP16(b + MAT_B + d0, bPtr0 + kt);
        CP16(b + d1,         aPtr1 + kt);
        CP16(b + MAT_B + d1, bPtr1 + kt);
    };

    load_stage(0, 0);
    CP_COMMIT();

    for (int c = 0; c < NITER; c++) {
        if (c + 1 < NITER) {
            load_stage((c + 1) & 1, (c + 1) * 32);
            CP_COMMIT();
            CP_WAIT(1);
        } else {
            CP_WAIT(0);
        }
        __syncthreads();

        const uint32_t sb = smb + (c & 1) * STG_B;
        #pragma unroll
        for (int ks = 0; ks < 2; ks++) {
            const uint32_t ko = ks * 32;
            uint32_t aH[2][4], bfr[4][4];
            #pragma unroll
            for (int mt = 0; mt < 2; mt++)
                ldsm_x4(aH[mt], sb + aoff + mt * (16 * PITCH * 2) + ko);
            #pragma unroll
            for (int n4 = 0; n4 < 4; n4++)
                ldsm_x4(bfr[n4], sb + MAT_B + boff + n4 * (16 * PITCH * 2) + ko);
            #pragma unroll
            for (int mt = 0; mt < 2; mt++)
                #pragma unroll
                for (int nt = 0; nt < 8; nt++)
                    mma16816(acc[mt][nt], aH[mt], bfr[nt >> 1][nt & 1], bfr[nt >> 1][2 + (nt & 1)]);
        }
        __syncthreads();
    }

    // ---- epilogue ----
    const int colb = nb * 128 + warp_n * 64 + (lane & 3) * 2;
    const float* bp = bias + (size_t)l * Ntot + colb;

    if constexpr (FUSE) {
        // router: fold relu + W_r2 dot + sigmoid; no C store (Ntot==RR, nb==0)
        __shared__ float sLog[2][128];
        const float* w2 = W_r2 + l * RR + colb;
        float part[2][2];
        #pragma unroll
        for (int mt = 0; mt < 2; mt++)
            #pragma unroll
            for (int half = 0; half < 2; half++) {
                float s = 0.0f;
                #pragma unroll
                for (int nt = 0; nt < 8; nt++) {
                    float vx = fmaxf(acc[mt][nt][half * 2 + 0] + bp[nt * 8],     0.f);
                    float vy = fmaxf(acc[mt][nt][half * 2 + 1] + bp[nt * 8 + 1], 0.f);
                    s = fmaf(vx, w2[nt * 8], s);
                    s = fmaf(vy, w2[nt * 8 + 1], s);
                }
                part[mt][half] = s;
            }
        #pragma unroll
        for (int o = 1; o <= 2; o <<= 1) {
            #pragma unroll
            for (int mt = 0; mt < 2; mt++)
                #pragma unroll
                for (int half = 0; half < 2; half++)
                    part[mt][half] += __shfl_xor_sync(0xFFFFFFFFu, part[mt][half], o);
        }
        if ((lane & 3) == 0) {
            #pragma unroll
            for (int mt = 0; mt < 2; mt++)
                #pragma unroll
                for (int half = 0; half < 2; half++) {
                    int rl = warp_m * 32 + mt * 16 + (lane >> 2) + half * 8;
                    sLog[warp_n][rl] = part[mt][half];
                }
        }
        __syncthreads();
        if (tid < 128) {
            float x = sLog[0][tid] + sLog[1][tid] + b_r2[l];
            g_probs[l * TT + mb * 128 + tid] = 1.0f / (1.0f + expf(-x));
        }
    } else {
        #pragma unroll
        for (int mt = 0; mt < 2; mt++) {
            #pragma unroll
            for (int half = 0; half < 2; half++) {
                int rl = warp_m * 32 + mt * 16 + (lane >> 2) + half * 8;
                int grow = s_rows[rl];
                float* dst = Cout + ((size_t)l * TT + grow) * Ntot + colb;
                #pragma unroll
                for (int nt = 0; nt < 8; nt++) {
                    float vx = acc[mt][nt][half * 2 + 0] + bp[nt * 8];
                    float vy = acc[mt][nt][half * 2 + 1] + bp[nt * 8 + 1];
                    *(float2*)(dst + nt * 8) = make_float2(vx, vy);
                }
            }
        }
    }
}

// =====================================================================
// exact rank on (approx) probs -> selected flag + boundary window capture
// =====================================================================
__global__ void rank_kernel() {
    __shared__ float sp[TT];
    int l = blockIdx.x;
    for (int t = threadIdx.x; t < TT; t += blockDim.x) sp[t] = g_probs[l * TT + t];
    __syncthreads();
    for (int t = threadIdx.x; t < TT; t += blockDim.x) {
        float pt = sp[t];
        int rank = 0;
        for (int s = 0; s < TT; s++) {
            float ps = sp[s];
            rank += (ps > pt) || (ps == pt && s < t);
        }
        g_flag[l * TT + t] = (rank < KCAP) ? 1 : 0;
        if (rank >= KCAP - HW && rank < KCAP + HW)
            g_bnd[l * WIN + (rank - (KCAP - HW))] = t;
    }
}

// =====================================================================
// exact fp32 router probs for FTOK boundary tokens per block.
// 128 blocks; W_r1 value held in a register and reused across 8 tokens
// (cuts W_r1 traffic 8x vs one-token-per-block). Partial-sum k-ranges and
// the 128-lane reduction tree are bit-identical to the 1-token version.
// =====================================================================
__global__ void fixup_probs_kernel(const float* __restrict__ hidden,
                                   const float* __restrict__ W_r1,
                                   const float* __restrict__ b_r1,
                                   const float* __restrict__ W_r2,
                                   const float* __restrict__ b_r2) {
    extern __shared__ float sh[];            // [FTOK][DD]
    __shared__ float red [FTOK][256];
    __shared__ float red2[FTOK][128];
    const int b = blockIdx.x;                // 0 .. LL*WIN/FTOK-1
    const int l   = b / (WIN / FTOK);
    const int grp = b % (WIN / FTOK);
    const int tid = threadIdx.x;

    #pragma unroll
    for (int j = 0; j < FTOK; j++) {
        int t = g_bnd[l * WIN + grp * FTOK + j];
        const float4* hrow = (const float4*)(hidden + ((size_t)l * TT + t) * DD);
        float4* dst = (float4*)(sh + j * DD);
        for (int q = tid; q < DD / 4; q += 256) dst[q] = hrow[q];
    }
    __syncthreads();

    const int r = tid & 127, kh = tid >> 7;
    const float* W1 = W_r1 + (size_t)l * DD * RR + r;
    float acc[FTOK];
    #pragma unroll
    for (int j = 0; j < FTOK; j++) acc[j] = 0.0f;
    #pragma unroll 4
    for (int k = kh * (DD / 2); k < (kh + 1) * (DD / 2); k++) {
        float w = W1[(size_t)k * RR];
        #pragma unroll
        for (int j = 0; j < FTOK; j++) acc[j] = fmaf(sh[j * DD + k], w, acc[j]);
    }
    #pragma unroll
    for (int j = 0; j < FTOK; j++) red[j][tid] = acc[j];
    __syncthreads();

    if (tid < 128) {
        float b1 = b_r1[l * RR + tid];
        float w2 = W_r2[l * RR + tid];
        #pragma unroll
        for (int j = 0; j < FTOK; j++) {
            float v = red[j][tid] + red[j][tid + 128];
            red2[j][tid] = fmaxf(v + b1, 0.0f) * w2;
        }
    }
    __syncthreads();
    for (int o = 64; o >= 1; o >>= 1) {
        if (tid < o) {
            #pragma unroll
            for (int j = 0; j < FTOK; j++) red2[j][tid] += red2[j][tid + o];
        }
        __syncthreads();
    }
    if (tid < FTOK) {
        float x = red2[tid][0] + b_r2[l];
        g_bndp[l * WIN + grp * FTOK + tid] = 1.0f / (1.0f + expf(-x));
    }
}

// =====================================================================
// re-rank boundary tokens with exact probs (in smem), then token-ordered
// compaction — one launch, flags never round-trip through global.
// =====================================================================
__global__ void fixup_compact_kernel() {
    __shared__ float wp[WIN];
    __shared__ int   wt[WIN];
    __shared__ int   fl[TT];
    int l = blockIdx.x, tid = threadIdx.x;
    if (tid < WIN) { wp[tid] = g_bndp[l * WIN + tid]; wt[tid] = g_bnd[l * WIN + tid]; }
    for (int t = tid; t < TT; t += blockDim.x) fl[t] = g_flag[l * TT + t];
    __syncthreads();
    if (tid < WIN) {
        float pt = wp[tid];
        int tt = wt[tid];
        int r = 0;
        #pragma unroll
        for (int s = 0; s < WIN; s++) {
            float ps = wp[s];
            r += (ps > pt) || (ps == pt && wt[s] < tt);
        }
        fl[tt] = (r < HW) ? 1 : 0;
    }
    __syncthreads();
    for (int t = tid; t < TT; t += blockDim.x) {
        int before = 0;
        for (int s = 0; s < t; s++) before += fl[s];
        if (fl[t]) g_sel[l * KCAP + before] = t;
        else       g_idx0[l * KCAP + (t - before)] = t;
    }
}

// =====================================================================
// selected rows: out = ((1-p)+p) * s2
// =====================================================================
__global__ void copy_sel_kernel(const float* __restrict__ s2,
                                float* __restrict__ out) {
    int b = blockIdx.x;
    int l = b >> 10;
    int t = g_sel[b];
    float p = g_probs[l * TT + t];
    float m = (1.0f - p) + p;
    size_t off = ((size_t)l * TT + t) * DD;
    const float4* src = (const float4*)(s2 + off);
    float4*       dst = (float4*)(out + off);
    #pragma unroll
    for (int i = threadIdx.x; i < DD / 4; i += 256) {
        float4 v = src[i];
        dst[i] = make_float4(m * v.x, m * v.y, m * v.z, m * v.w);
    }
}

// =====================================================================
extern "C" void kernel_launch(void* const* d_in, const int* in_sizes, int n_in,
                              void* d_out, int out_size) {
    const float* hidden = (const float*)d_in[0];
    const float* s2     = (const float*)d_in[1];
    const float* W_r1   = (const float*)d_in[2];
    const float* b_r1   = (const float*)d_in[3];
    const float* W_r2   = (const float*)d_in[4];
    const float* b_r2   = (const float*)d_in[5];
    const float* W_s1   = (const float*)d_in[6];
    const float* b_s1   = (const float*)d_in[7];
    float* out = (float*)d_out;

    const int SMEM = 2 * STG_B;   // 40960
    const int SMEM_FIX = FTOK * DD * 4;   // 65536
    cudaFuncSetAttribute(hmma_gemm_kernel<true,  false>,
                         cudaFuncAttributeMaxDynamicSharedMemorySize, SMEM);
    cudaFuncSetAttribute(hmma_gemm_kernel<false, true>,
                         cudaFuncAttributeMaxDynamicSharedMemorySize, SMEM);
    cudaFuncSetAttribute(fixup_probs_kernel,
                         cudaFuncAttributeMaxDynamicSharedMemorySize, SMEM_FIX);

    // precompute fp16 copies (single stream — R10 showed overlap starves the chain)
    split_hidden_kernel<<<32768, 512>>>((const float4*)hidden);
    transpose_split_kernel<false><<<dim3(64, 4, 16),  dim3(32, 8)>>>(W_r1, DD, RR);
    transpose_split_kernel<true ><<<dim3(64, 64, 16), dim3(32, 8)>>>(W_s1, DD, DD);

    // router GEMM with fused relu+logits+sigmoid epilogue -> g_probs
    hmma_gemm_kernel<false, true><<<dim3(16, 1, LL), 256, SMEM>>>(
        b_r1, nullptr, RR, W_r2, b_r2);
    rank_kernel<<<LL, 1024>>>();
    fixup_probs_kernel<<<LL * (WIN / FTOK), 256, SMEM_FIX>>>(
        hidden, W_r1, b_r1, W_r2, b_r2);
    fixup_compact_kernel<<<LL, 1024>>>();
    copy_sel_kernel<<<LL * KCAP, 256>>>(s2, out);

    // s1 GEMM on unselected rows (token-ordered gather)
    hmma_gemm_kernel<true, false><<<dim3(8, 16, LL), 256, SMEM>>>(
        b_s1, out, DD, nullptr, nullptr);
}

// round 13
// speedup vs baseline: 1.1545x; 1.1545x over previous
#include <cuda_runtime.h>
#include <cuda_fp16.h>
#include <math.h>
#include <stdint.h>

// Problem dims
#define LL 16
#define TT 2048
#define DD 2048
#define RR 128
#define KCAP 1024
#define WIN 64          // boundary fixup window (ranks KCAP-32 .. KCAP+32)
#define HW (WIN / 2)

// ---------------- scratch (device globals) ----------------
__device__ float g_probs[LL * TT];
__device__ int   g_flag[LL * TT];          // 1 = selected (s2 path)
__device__ int   g_sel [LL * KCAP];        // selected tokens, token order
__device__ int   g_idx0[LL * KCAP];        // unselected tokens, token order
__device__ int   g_bnd [LL * WIN];         // boundary tokens (approx-rank order)
__device__ float g_bndp[LL * WIN];         // exact probs for boundary tokens
// fp16 copies (round-to-nearest)
__device__ __half g_A   [(size_t)LL * TT * DD];   // hidden
__device__ __half g_Ws1t[(size_t)LL * DD * DD];   // W_s1^T [L,N,K]
__device__ __half g_Wr1t[(size_t)LL * RR * DD];   // W_r1^T [L,R,K]

// ---------------- PTX helpers (baseline ISA only) ----------------
__device__ __forceinline__ uint32_t smem_u32(const void* p) {
    uint32_t a;
    asm("{ .reg .u64 t; cvta.to.shared.u64 t, %1; cvt.u32.u64 %0, t; }" : "=r"(a) : "l"(p));
    return a;
}
#define CP16(dst, src) \
    asm volatile("cp.async.cg.shared.global [%0], [%1], 16;" :: "r"(dst), "l"(src))
#define CP_COMMIT() asm volatile("cp.async.commit_group;")
#define CP_WAIT(n)  asm volatile("cp.async.wait_group %0;" :: "n"(n))

__device__ __forceinline__ void ldsm_x4(uint32_t* r, uint32_t addr) {
    asm volatile("ldmatrix.sync.aligned.m8n8.x4.shared.b16 {%0,%1,%2,%3}, [%4];"
                 : "=r"(r[0]), "=r"(r[1]), "=r"(r[2]), "=r"(r[3]) : "r"(addr));
}
__device__ __forceinline__ void mma16816(float* d, const uint32_t* a,
                                         uint32_t b0, uint32_t b1) {
    asm volatile(
        "mma.sync.aligned.m16n8k16.row.col.f32.f16.f16.f32 "
        "{%0,%1,%2,%3}, {%4,%5,%6,%7}, {%8,%9}, {%0,%1,%2,%3};"
        : "+f"(d[0]), "+f"(d[1]), "+f"(d[2]), "+f"(d[3])
        : "r"(a[0]), "r"(a[1]), "r"(a[2]), "r"(a[3]), "r"(b0), "r"(b1));
}

// =====================================================================
// hidden f32 -> g_A fp16 (RN)
// =====================================================================
__global__ void split_hidden_kernel(const float4* __restrict__ h) {
    size_t i = (size_t)blockIdx.x * blockDim.x + threadIdx.x;   // < L*T*D/4
    float4 v = h[i];
    __half2 p0 = make_half2(__float2half_rn(v.x), __float2half_rn(v.y));
    __half2 p1 = make_half2(__float2half_rn(v.z), __float2half_rn(v.w));
    ((uint2*)g_A)[i] = make_uint2(*(uint32_t*)&p0, *(uint32_t*)&p1);
}

// =====================================================================
// W[l,k,n] f32 -> Wt[l,n,k] fp16 (RN)
// =====================================================================
template<bool S1>
__global__ void transpose_split_kernel(const float* __restrict__ W, int K, int N) {
    __shared__ float tile[32][33];
    const int l  = blockIdx.z;
    const int k0 = blockIdx.x * 32;
    const int n0 = blockIdx.y * 32;
    const int tx = threadIdx.x, ty = threadIdx.y;
    const float* Wl = W + (size_t)l * K * N;
    #pragma unroll
    for (int r = 0; r < 4; r++)
        tile[ty + r * 8][tx] = Wl[(size_t)(k0 + ty + r * 8) * N + n0 + tx];
    __syncthreads();
    __half* Wt = S1 ? g_Ws1t : g_Wr1t;
    #pragma unroll
    for (int r = 0; r < 4; r++) {
        int n = n0 + ty + r * 8;
        float v = tile[tx][ty + r * 8];
        Wt[((size_t)l * N + n) * K + k0 + tx] = __float2half_rn(v);
    }
}

// =====================================================================
// HMMA GEMM (fp16 single-pass, fp32 accum): C[128x128 tile] = A @ B^T.
// PITCH-40 smem, 2-stage cp.async, 256 threads (warps 4x2), 2 CTAs/SM.
// FUSE: router mode — epilogue computes sigmoid(relu(acc+b1).W_r2+b2).
// GATHER mode: blocks with mb>=8 are COPY blocks (out = m*s2 on selected
// rows) — absorbed into the GEMM launch's bandwidth slack.
// =====================================================================
#define PITCH 40                    // fp16 elts per smem row (32 + 8 pad)
#define MAT_ELT (128 * PITCH)       // 5120 elts per matrix
#define MAT_B   (MAT_ELT * 2)       // 10240 bytes
#define STG_B   (2 * MAT_B)         // A,B : 20480 bytes
#define NITER   (DD / 32)           // 64

template<bool GATHER, bool FUSE>
__global__ __launch_bounds__(256, 2)
void hmma_gemm_kernel(const float* __restrict__ bias,
                      float* __restrict__ Cout, int Ntot,
                      const float* __restrict__ W_r2,
                      const float* __restrict__ b_r2,
                      const float* __restrict__ s2p) {
    const int mb = blockIdx.x, nb = blockIdx.y, l = blockIdx.z;

    if constexpr (GATHER) {
        if (mb >= 8) {
            // ---- copy block: 16 selected rows, out = ((1-p)+p) * s2
            const int c = (mb - 8) * 16 + nb;   // 0..63
            #pragma unroll
            for (int j = 0; j < 16; j++) {
                int t = g_sel[l * KCAP + c * 16 + j];
                float p = g_probs[l * TT + t];
                float m = (1.0f - p) + p;
                size_t off = ((size_t)l * TT + t) * DD;
                const float4* src = (const float4*)(s2p + off);
                float4*       dst = (float4*)(Cout + off);
                for (int i = threadIdx.x; i < DD / 4; i += 256) {
                    float4 v = src[i];
                    dst[i] = make_float4(m * v.x, m * v.y, m * v.z, m * v.w);
                }
            }
            return;
        }
    }

    extern __shared__ __align__(16) char smraw[];
    const uint32_t smb = smem_u32(smraw);

    const int tid  = threadIdx.x;
    const int lane = tid & 31;
    const int wid  = tid >> 5;
    const int warp_m = wid & 3;
    const int warp_n = wid >> 2;

    __shared__ int s_rows[128];
    if (tid < 128)
        s_rows[tid] = GATHER ? g_idx0[l * KCAP + mb * 128 + tid] : (mb * 128 + tid);
    __syncthreads();

    const int c0 = tid, c1 = tid + 256;
    const int r0 = c0 >> 2, r1 = c1 >> 2;
    const int f0 = (c0 & 3) * 8, f1 = (c1 & 3) * 8;
    const __half* __restrict__ Aall = g_A + (size_t)l * TT * DD;
    const __half* __restrict__ Wt =
        (GATHER ? g_Ws1t : g_Wr1t) + ((size_t)l * Ntot + nb * 128) * DD;
    const __half* aPtr0 = Aall + (size_t)s_rows[r0] * DD + f0;
    const __half* aPtr1 = Aall + (size_t)s_rows[r1] * DD + f1;
    const __half* bPtr0 = Wt + (size_t)r0 * DD + f0;
    const __half* bPtr1 = Wt + (size_t)r1 * DD + f1;
    const uint32_t d0 = (uint32_t)(r0 * PITCH + f0) * 2;
    const uint32_t d1 = (uint32_t)(r1 * PITCH + f1) * 2;

    float acc[2][8][4];
    #pragma unroll
    for (int mt = 0; mt < 2; mt++)
        #pragma unroll
        for (int nt = 0; nt < 8; nt++)
            #pragma unroll
            for (int q = 0; q < 4; q++) acc[mt][nt][q] = 0.0f;

    const uint32_t aoff = (uint32_t)((warp_m * 32 + (lane & 15)) * PITCH + (lane >> 4) * 8) * 2;
    const uint32_t boff = (uint32_t)((warp_n * 64 + (lane & 15)) * PITCH + (lane >> 4) * 8) * 2;

    auto load_stage = [&](int s, int kt) {
        uint32_t b = smb + s * STG_B;
        CP16(b + d0,         aPtr0 + kt);
        CP16(b + MAT_B + d0, bPtr0 + kt);
        CP16(b + d1,         aPtr1 + kt);
        CP16(b + MAT_B + d1, bPtr1 + kt);
    };

    load_stage(0, 0);
    CP_COMMIT();

    for (int c = 0; c < NITER; c++) {
        if (c + 1 < NITER) {
            load_stage((c + 1) & 1, (c + 1) * 32);
            CP_COMMIT();
            CP_WAIT(1);
        } else {
            CP_WAIT(0);
        }
        __syncthreads();

        const uint32_t sb = smb + (c & 1) * STG_B;
        #pragma unroll
        for (int ks = 0; ks < 2; ks++) {
            const uint32_t ko = ks * 32;
            uint32_t aH[2][4], bfr[4][4];
            #pragma unroll
            for (int mt = 0; mt < 2; mt++)
                ldsm_x4(aH[mt], sb + aoff + mt * (16 * PITCH * 2) + ko);
            #pragma unroll
            for (int n4 = 0; n4 < 4; n4++)
                ldsm_x4(bfr[n4], sb + MAT_B + boff + n4 * (16 * PITCH * 2) + ko);
            #pragma unroll
            for (int mt = 0; mt < 2; mt++)
                #pragma unroll
                for (int nt = 0; nt < 8; nt++)
                    mma16816(acc[mt][nt], aH[mt], bfr[nt >> 1][nt & 1], bfr[nt >> 1][2 + (nt & 1)]);
        }
        __syncthreads();
    }

    // ---- epilogue ----
    const int colb = nb * 128 + warp_n * 64 + (lane & 3) * 2;
    const float* bp = bias + (size_t)l * Ntot + colb;

    if constexpr (FUSE) {
        __shared__ float sLog[2][128];
        const float* w2 = W_r2 + l * RR + colb;
        float part[2][2];
        #pragma unroll
        for (int mt = 0; mt < 2; mt++)
            #pragma unroll
            for (int half = 0; half < 2; half++) {
                float s = 0.0f;
                #pragma unroll
                for (int nt = 0; nt < 8; nt++) {
                    float vx = fmaxf(acc[mt][nt][half * 2 + 0] + bp[nt * 8],     0.f);
                    float vy = fmaxf(acc[mt][nt][half * 2 + 1] + bp[nt * 8 + 1], 0.f);
                    s = fmaf(vx, w2[nt * 8], s);
                    s = fmaf(vy, w2[nt * 8 + 1], s);
                }
                part[mt][half] = s;
            }
        #pragma unroll
        for (int o = 1; o <= 2; o <<= 1) {
            #pragma unroll
            for (int mt = 0; mt < 2; mt++)
                #pragma unroll
                for (int half = 0; half < 2; half++)
                    part[mt][half] += __shfl_xor_sync(0xFFFFFFFFu, part[mt][half], o);
        }
        if ((lane & 3) == 0) {
            #pragma unroll
            for (int mt = 0; mt < 2; mt++)
                #pragma unroll
                for (int half = 0; half < 2; half++) {
                    int rl = warp_m * 32 + mt * 16 + (lane >> 2) + half * 8;
                    sLog[warp_n][rl] = part[mt][half];
                }
        }
        __syncthreads();
        if (tid < 128) {
            float x = sLog[0][tid] + sLog[1][tid] + b_r2[l];
            g_probs[l * TT + mb * 128 + tid] = 1.0f / (1.0f + expf(-x));
        }
    } else {
        #pragma unroll
        for (int mt = 0; mt < 2; mt++) {
            #pragma unroll
            for (int half = 0; half < 2; half++) {
                int rl = warp_m * 32 + mt * 16 + (lane >> 2) + half * 8;
                int grow = s_rows[rl];
                float* dst = Cout + ((size_t)l * TT + grow) * Ntot + colb;
                #pragma unroll
                for (int nt = 0; nt < 8; nt++) {
                    float vx = acc[mt][nt][half * 2 + 0] + bp[nt * 8];
                    float vy = acc[mt][nt][half * 2 + 1] + bp[nt * 8 + 1];
                    *(float2*)(dst + nt * 8) = make_float2(vx, vy);
                }
            }
        }
    }
}

// =====================================================================
// exact rank on (approx) probs -> selected flag + boundary window capture
// =====================================================================
__global__ void rank_kernel() {
    __shared__ float sp[TT];
    int l = blockIdx.x;
    for (int t = threadIdx.x; t < TT; t += blockDim.x) sp[t] = g_probs[l * TT + t];
    __syncthreads();
    for (int t = threadIdx.x; t < TT; t += blockDim.x) {
        float pt = sp[t];
        int rank = 0;
        for (int s = 0; s < TT; s++) {
            float ps = sp[s];
            rank += (ps > pt) || (ps == pt && s < t);
        }
        g_flag[l * TT + t] = (rank < KCAP) ? 1 : 0;
        if (rank >= KCAP - HW && rank < KCAP + HW)
            g_bnd[l * WIN + (rank - (KCAP - HW))] = t;
    }
}

// =====================================================================
// exact fp32 router prob for ONE boundary token per block (R11 version —
// 1024 small blocks; measured fast, do not re-batch)
// =====================================================================
__global__ void fixup_probs_kernel(const float* __restrict__ hidden,
                                   const float* __restrict__ W_r1,
                                   const float* __restrict__ b_r1,
                                   const float* __restrict__ W_r2,
                                   const float* __restrict__ b_r2) {
    __shared__ float sh[DD];
    __shared__ float red[256];
    int b = blockIdx.x;
    int l = b / WIN, slot = b % WIN;
    int t = g_bnd[l * WIN + slot];
    int tid = threadIdx.x;
    const float* hrow = hidden + ((size_t)l * TT + t) * DD;
    for (int k = tid; k < DD; k += 256) sh[k] = hrow[k];
    __syncthreads();

    int r = tid & 127, kh = tid >> 7;
    const float* W1 = W_r1 + (size_t)l * DD * RR + r;
    float a = 0.0f;
    #pragma unroll 4
    for (int k = kh * (DD / 2); k < (kh + 1) * (DD / 2); k++)
        a = fmaf(sh[k], W1[(size_t)k * RR], a);
    red[tid] = a;
    __syncthreads();
    if (tid < 128) {
        float v = red[tid] + red[tid + 128];
        v = fmaxf(v + b_r1[l * RR + tid], 0.0f) * W_r2[l * RR + tid];
        red[tid] = v;
    }
    __syncthreads();
    for (int o = 64; o >= 1; o >>= 1) {
        if (tid < o && o <= 64) red[tid] += red[tid + o];
        __syncthreads();
    }
    if (tid == 0) {
        float x = red[0] + b_r2[l];
        g_bndp[l * WIN + slot] = 1.0f / (1.0f + expf(-x));
    }
}

// =====================================================================
// re-rank the WIN boundary tokens with exact probs; update flags
// =====================================================================
__global__ void fixup_rank_kernel() {
    __shared__ float wp[WIN];
    __shared__ int   wt[WIN];
    int l = blockIdx.x, tid = threadIdx.x;
    if (tid < WIN) { wp[tid] = g_bndp[l * WIN + tid]; wt[tid] = g_bnd[l * WIN + tid]; }
    __syncthreads();
    if (tid < WIN) {
        float pt = wp[tid];
        int tt = wt[tid];
        int r = 0;
        #pragma unroll
        for (int s = 0; s < WIN; s++) {
            float ps = wp[s];
            r += (ps > pt) || (ps == pt && wt[s] < tt);
        }
        g_flag[l * TT + tt] = (r < HW) ? 1 : 0;
    }
}

// =====================================================================
// token-ordered compaction from flags
// =====================================================================
__global__ void compact_kernel() {
    __shared__ int fl[TT];
    int l = blockIdx.x;
    for (int t = threadIdx.x; t < TT; t += blockDim.x) fl[t] = g_flag[l * TT + t];
    __syncthreads();
    for (int t = threadIdx.x; t < TT; t += blockDim.x) {
        int before = 0;
        for (int s = 0; s < t; s++) before += fl[s];
        if (fl[t]) g_sel[l * KCAP + before] = t;
        else       g_idx0[l * KCAP + (t - before)] = t;
    }
}

// =====================================================================
extern "C" void kernel_launch(void* const* d_in, const int* in_sizes, int n_in,
                              void* d_out, int out_size) {
    const float* hidden = (const float*)d_in[0];
    const float* s2     = (const float*)d_in[1];
    const float* W_r1   = (const float*)d_in[2];
    const float* b_r1   = (const float*)d_in[3];
    const float* W_r2   = (const float*)d_in[4];
    const float* b_r2   = (const float*)d_in[5];
    const float* W_s1   = (const float*)d_in[6];
    const float* b_s1   = (const float*)d_in[7];
    float* out = (float*)d_out;

    const int SMEM = 2 * STG_B;   // 40960
    cudaFuncSetAttribute(hmma_gemm_kernel<true,  false>,
                         cudaFuncAttributeMaxDynamicSharedMemorySize, SMEM);
    cudaFuncSetAttribute(hmma_gemm_kernel<false, true>,
                         cudaFuncAttributeMaxDynamicSharedMemorySize, SMEM);

    // precompute fp16 copies (single stream)
    split_hidden_kernel<<<32768, 512>>>((const float4*)hidden);
    transpose_split_kernel<false><<<dim3(64, 4, 16),  dim3(32, 8)>>>(W_r1, DD, RR);
    transpose_split_kernel<true ><<<dim3(64, 64, 16), dim3(32, 8)>>>(W_s1, DD, DD);

    // router GEMM with fused relu+logits+sigmoid epilogue -> g_probs
    hmma_gemm_kernel<false, true><<<dim3(16, 1, LL), 256, SMEM>>>(
        b_r1, nullptr, RR, W_r2, b_r2, nullptr);
    rank_kernel<<<LL, 1024>>>();
    fixup_probs_kernel<<<LL * WIN, 256>>>(hidden, W_r1, b_r1, W_r2, b_r2);
    fixup_rank_kernel<<<LL, WIN>>>();
    compact_kernel<<<LL, 1024>>>();

    // s1 GEMM on unselected rows + fused copy blocks (mb 8..11) for selected
    hmma_gemm_kernel<true, false><<<dim3(12, 16, LL), 256, SMEM>>>(
        b_s1, out, DD, nullptr, nullptr, s2);
}